// round 1
// baseline (speedup 1.0000x reference)
#include <cuda_runtime.h>
#include <math.h>

#define NBINS 1024

__device__ double g_part[NBINS];

__global__ void mvce_init() {
    int i = blockIdx.x * blockDim.x + threadIdx.x;
    if (i < NBINS) g_part[i] = 0.0;
}

__device__ __forceinline__ float warp_max(float v) {
    #pragma unroll
    for (int o = 16; o > 0; o >>= 1) v = fmaxf(v, __shfl_xor_sync(0xffffffffu, v, o));
    return v;
}
__device__ __forceinline__ float warp_sum(float v) {
    #pragma unroll
    for (int o = 16; o > 0; o >>= 1) v += __shfl_xor_sync(0xffffffffu, v, o);
    return v;
}

// One CTA per row. C must be a multiple of 4 and <= 4*blockDim.x (C=1000, 256 thr).
// Each thread keeps its float4 of output/target/exp in registers across all phases:
// global memory is touched exactly once per element.
__global__ void __launch_bounds__(256) mvce_row(const float* __restrict__ outp,
                                                const float* __restrict__ tgtp,
                                                int C) {
    const int row  = blockIdx.x;
    const int tid  = threadIdx.x;
    const int lane = tid & 31;
    const int wid  = tid >> 5;
    const int nvec = C >> 2;

    const float4* o4 = reinterpret_cast<const float4*>(outp + (size_t)row * C);
    const float4* t4 = reinterpret_cast<const float4*>(tgtp + (size_t)row * C);

    float4 o, t;
    if (tid < nvec) {
        o = o4[tid];
        t = t4[tid];
    } else {
        o = make_float4(-3.0e38f, -3.0e38f, -3.0e38f, -3.0e38f);
        t = make_float4(0.f, 0.f, 0.f, 0.f);
    }

    __shared__ float swarp[4][8];
    __shared__ float bcast[5];   // m, Sn, Tn, An, Np

    // ---- Phase 1: row max ----
    float mx = warp_max(fmaxf(fmaxf(o.x, o.y), fmaxf(o.z, o.w)));
    if (lane == 0) swarp[0][wid] = mx;
    __syncthreads();
    if (tid == 0) {
        float m = swarp[0][0];
        #pragma unroll
        for (int i = 1; i < 8; i++) m = fmaxf(m, swarp[0][i]);
        bcast[0] = m;
    }
    __syncthreads();
    const float m = bcast[0];

    // ---- Phase 2: shifted exps + negative-set sums ----
    float4 e;
    e.x = __expf(o.x - m);
    e.y = __expf(o.y - m);
    e.z = __expf(o.z - m);
    e.w = __expf(o.w - m);

    float sn = 0.f, tn = 0.f, an = 0.f, np = 0.f;
    {
        // padding lanes have t=0 (neg) and e=exp(-huge)=0 -> contribute nothing
        bool ngx = t.x <= 0.5f; sn += ngx ? e.x : 0.f; tn += ngx ? t.x : 0.f; an += ngx ? t.x * o.x : 0.f; np += ngx ? 0.f : 1.f;
        bool ngy = t.y <= 0.5f; sn += ngy ? e.y : 0.f; tn += ngy ? t.y : 0.f; an += ngy ? t.y * o.y : 0.f; np += ngy ? 0.f : 1.f;
        bool ngz = t.z <= 0.5f; sn += ngz ? e.z : 0.f; tn += ngz ? t.z : 0.f; an += ngz ? t.z * o.z : 0.f; np += ngz ? 0.f : 1.f;
        bool ngw = t.w <= 0.5f; sn += ngw ? e.w : 0.f; tn += ngw ? t.w : 0.f; an += ngw ? t.w * o.w : 0.f; np += ngw ? 0.f : 1.f;
    }
    sn = warp_sum(sn); tn = warp_sum(tn); an = warp_sum(an); np = warp_sum(np);
    if (lane == 0) { swarp[0][wid] = sn; swarp[1][wid] = tn; swarp[2][wid] = an; swarp[3][wid] = np; }
    __syncthreads();
    if (tid == 0) {
        float a = 0.f, b = 0.f, c = 0.f, d = 0.f;
        #pragma unroll
        for (int i = 0; i < 8; i++) { a += swarp[0][i]; b += swarp[1][i]; c += swarp[2][i]; d += swarp[3][i]; }
        bcast[1] = a; bcast[2] = b; bcast[3] = c; bcast[4] = d;
    }
    __syncthreads();
    const float Sn = bcast[1];
    const float Tn = bcast[2];
    const float An = bcast[3];
    const float Np = bcast[4];

    // ---- Phase 3: per-positive loss ----
    float L = 0.f;
    if (t.x > 0.5f) L += (Tn + t.x) * (m + __logf(Sn + e.x)) - An - t.x * o.x;
    if (t.y > 0.5f) L += (Tn + t.y) * (m + __logf(Sn + e.y)) - An - t.y * o.y;
    if (t.z > 0.5f) L += (Tn + t.z) * (m + __logf(Sn + e.z)) - An - t.z * o.z;
    if (t.w > 0.5f) L += (Tn + t.w) * (m + __logf(Sn + e.w)) - An - t.w * o.w;

    L = warp_sum(L);
    if (lane == 0) swarp[0][wid] = L;
    __syncthreads();
    if (tid == 0) {
        float Ls = 0.f;
        #pragma unroll
        for (int i = 0; i < 8; i++) Ls += swarp[0][i];
        float row_loss = (Np > 0.f) ? (Ls / Np)
                                    : (Tn * (m + __logf(Sn)) - An);
        atomicAdd(&g_part[row & (NBINS - 1)], (double)row_loss);
    }
}

__global__ void mvce_final(float* __restrict__ out, int B) {
    __shared__ double sd[8];
    const int tid = threadIdx.x;  // 256 threads
    double v = 0.0;
    for (int i = tid; i < NBINS; i += 256) v += g_part[i];
    #pragma unroll
    for (int o = 16; o > 0; o >>= 1) v += __shfl_xor_sync(0xffffffffu, v, o);
    if ((tid & 31) == 0) sd[tid >> 5] = v;
    __syncthreads();
    if (tid == 0) {
        double s = 0.0;
        #pragma unroll
        for (int i = 0; i < 8; i++) s += sd[i];
        out[0] = (float)(s / (double)B);
    }
}

extern "C" void kernel_launch(void* const* d_in, const int* in_sizes, int n_in,
                              void* d_out, int out_size) {
    const float* outp = (const float*)d_in[0];
    const float* tgtp = (const float*)d_in[1];
    const int C = 1000;               // fixed per problem shape
    const int B = in_sizes[0] / C;    // 65536

    mvce_init<<<(NBINS + 255) / 256, 256>>>();
    mvce_row<<<B, 256>>>(outp, tgtp, C);
    mvce_final<<<1, 256>>>((float*)d_out, B);
}